// round 1
// baseline (speedup 1.0000x reference)
#include <cuda_runtime.h>
#include <cuda_bf16.h>

#define Qn 256
#define Kn 256
#define D  32
#define NT 256

// One CTA per batch. Thread t owns query row t.
// K,V staged in dynamic smem (64KB). Softmax without max-subtraction
// (scores are ~N(0,sqrt(2)), bounded ~8, safe in fp32).
// Keys >= valid_len contribute exactly 0 (exp(-1e6) == 0 numerically),
// so we simply stop the key loop at valid_len (uniform per CTA).
__global__ __launch_bounds__(NT) void attn_fp32_kernel(
    const float* __restrict__ q,
    const float* __restrict__ k,
    const float* __restrict__ v,
    const int*   __restrict__ vlen,
    const float* __restrict__ mask,
    float*       __restrict__ out)
{
    extern __shared__ float4 smem[];
    float4* sK = smem;            // Kn*8 float4 = 32KB
    float4* sV = smem + Kn * 8;   // 32KB

    const int b   = blockIdx.x;
    const int tid = threadIdx.x;

    // Stage K,V for this batch (coalesced float4 loads)
    const float4* gK = (const float4*)(k + (size_t)b * Kn * D);
    const float4* gV = (const float4*)(v + (size_t)b * Kn * D);
    #pragma unroll
    for (int i = tid; i < Kn * 8; i += NT) {
        sK[i] = gK[i];
        sV[i] = gV[i];
    }

    const int vl = vlen[b];
    const int w  = (b >> 3) & 63;   // window index: (b / NUM_HEADS) % num_windows

    // Per-thread query row into registers
    const float4* gQ = (const float4*)(q + ((size_t)b * Qn + tid) * D);
    float4 q4[8];
    #pragma unroll
    for (int j = 0; j < 8; j++) q4[j] = gQ[j];

    // Mask row for this (window, query): contiguous 1KB, read in float4 bursts
    const float4* gM = (const float4*)(mask + ((size_t)w * Qn + tid) * Kn);

    __syncthreads();

    const float scale = 0.17677669529663687f;  // 1/sqrt(32)

    float4 acc[8];
    #pragma unroll
    for (int j = 0; j < 8; j++) acc[j] = make_float4(0.f, 0.f, 0.f, 0.f);
    float l = 0.f;

    for (int k0 = 0; k0 < vl; k0 += 16) {
        // Prefetch 16 mask values (64B contiguous per thread)
        float4 m4[4];
        #pragma unroll
        for (int j = 0; j < 4; j++) m4[j] = gM[(k0 >> 2) + j];
        const float* mv = (const float*)m4;

        #pragma unroll
        for (int kk = 0; kk < 16; kk++) {
            const int kidx = k0 + kk;
            // dot(q, K[kidx]) — LDS.128 broadcasts, conflict-free
            const float4* kr = &sK[kidx * 8];
            float s = 0.f;
            #pragma unroll
            for (int j = 0; j < 8; j++) {
                float4 kv = kr[j];
                s += q4[j].x * kv.x + q4[j].y * kv.y
                   + q4[j].z * kv.z + q4[j].w * kv.w;
            }
            s = s * scale + mv[kk];
            float p = (kidx < vl) ? __expf(s) : 0.f;
            l += p;
            const float4* vr = &sV[kidx * 8];
            #pragma unroll
            for (int j = 0; j < 8; j++) {
                float4 vv = vr[j];
                acc[j].x += p * vv.x;
                acc[j].y += p * vv.y;
                acc[j].z += p * vv.z;
                acc[j].w += p * vv.w;
            }
        }
    }

    const float inv = 1.f / l;
    float4* gO = (float4*)(out + ((size_t)b * Qn + tid) * D);
    #pragma unroll
    for (int j = 0; j < 8; j++) {
        gO[j] = make_float4(acc[j].x * inv, acc[j].y * inv,
                            acc[j].z * inv, acc[j].w * inv);
    }
}

extern "C" void kernel_launch(void* const* d_in, const int* in_sizes, int n_in,
                              void* d_out, int out_size) {
    const float* q    = (const float*)d_in[0];
    const float* k    = (const float*)d_in[1];
    const float* v    = (const float*)d_in[2];
    const int*   vlen = (const int*)d_in[3];
    const float* mask = (const float*)d_in[4];
    float* out = (float*)d_out;

    const int n = in_sizes[3];          // number of batches (valid_lens count)
    const int smem_bytes = 2 * Kn * D * (int)sizeof(float);  // 64KB

    static bool attr_set = false;
    if (!attr_set) {
        cudaFuncSetAttribute(attn_fp32_kernel,
                             cudaFuncAttributeMaxDynamicSharedMemorySize,
                             smem_bytes);
        attr_set = true;
    }

    attn_fp32_kernel<<<n, NT, smem_bytes>>>(q, k, v, vlen, mask, out);
}

// round 2
// speedup vs baseline: 1.3655x; 1.3655x over previous
#include <cuda_runtime.h>
#include <cuda_bf16.h>

#define Qn 256
#define Kn 256
#define D  32
#define NT 128   // 128 threads, each owns 2 query rows (t and t+128)

typedef unsigned long long u64;

// ---- packed f32x2 helpers (Blackwell dual-FMA; ptxas never auto-fuses) ----
__device__ __forceinline__ void fma2(u64& d, u64 a, u64 b) {
    asm("fma.rn.f32x2 %0, %1, %2, %0;" : "+l"(d) : "l"(a), "l"(b));
}
__device__ __forceinline__ u64 mul2(u64 a, u64 b) {
    u64 r; asm("mul.rn.f32x2 %0, %1, %2;" : "=l"(r) : "l"(a), "l"(b)); return r;
}
__device__ __forceinline__ u64 pack2(float x) {
    u64 r; asm("mov.b64 %0, {%1, %1};" : "=l"(r) : "f"(x)); return r;
}
__device__ __forceinline__ float2 unpack2(u64 a) {
    float2 f; asm("mov.b64 {%0, %1}, %2;" : "=f"(f.x), "=f"(f.y) : "l"(a)); return f;
}

// One CTA per batch. K,V staged in smem (64KB). No softmax max-subtraction
// (scores ~N(0,sqrt(2)), safe in fp32). Keys >= valid_len contribute exactly 0,
// loop stops at valid_len (uniform per CTA).
__global__ __launch_bounds__(NT, 2) void attn_fp32x2_kernel(
    const float* __restrict__ q,
    const float* __restrict__ k,
    const float* __restrict__ v,
    const int*   __restrict__ vlen,
    const float* __restrict__ mask,
    float*       __restrict__ out)
{
    extern __shared__ char smem[];           // [0,32K): K rows, [32K,64K): V rows
    float4* sKV = (float4*)smem;

    const int b   = blockIdx.x;
    const int tid = threadIdx.x;

    // Stage K,V (coalesced float4)
    const float4* gK = (const float4*)(k + (size_t)b * Kn * D);
    const float4* gV = (const float4*)(v + (size_t)b * Kn * D);
    #pragma unroll
    for (int i = tid; i < Kn * 8; i += NT) {
        sKV[i]            = gK[i];
        sKV[i + Kn * 8]   = gV[i];
    }

    const int vl = vlen[b];
    const int w  = (b >> 3) & 63;            // (b / NUM_HEADS) % num_windows
    const float scale = 0.17677669529663687f; // 1/sqrt(32)
    const u64 scale2 = pack2(scale);

    // Load 2 query rows, pre-scaled, as 16 packed f32x2 each
    u64 qr[2][16];
    #pragma unroll
    for (int qi = 0; qi < 2; qi++) {
        const ulonglong2* gQ =
            (const ulonglong2*)(q + ((size_t)b * Qn + tid + qi * NT) * D);
        #pragma unroll
        for (int j = 0; j < 8; j++) {
            ulonglong2 t = gQ[j];
            qr[qi][2*j]   = mul2(t.x, scale2);
            qr[qi][2*j+1] = mul2(t.y, scale2);
        }
    }

    const float4* gM0 = (const float4*)(mask + ((size_t)w * Qn + tid)      * Kn);
    const float4* gM1 = (const float4*)(mask + ((size_t)w * Qn + tid + NT) * Kn);

    u64 acc[2][16];
    #pragma unroll
    for (int j = 0; j < 16; j++) { acc[0][j] = 0ULL; acc[1][j] = 0ULL; }
    float l0 = 0.f, l1 = 0.f;

    __syncthreads();

    for (int k0 = 0; k0 < vl; k0 += 8) {
        // prefetch mask (8 keys x 2 queries, contiguous per thread)
        float m0[8], m1[8];
        *(float4*)&m0[0] = gM0[(k0 >> 2)];
        *(float4*)&m0[4] = gM0[(k0 >> 2) + 1];
        *(float4*)&m1[0] = gM1[(k0 >> 2)];
        *(float4*)&m1[4] = gM1[(k0 >> 2) + 1];

        #pragma unroll
        for (int kk = 0; kk < 8; kk++) {
            const int kidx = k0 + kk;
            // --- QK dots (packed along d) ---
            const ulonglong2* kr = (const ulonglong2*)(smem + kidx * 128);
            u64 s0 = 0ULL, s1 = 0ULL;
            #pragma unroll
            for (int j = 0; j < 8; j++) {
                ulonglong2 kv = kr[j];
                fma2(s0, qr[0][2*j],   kv.x);
                fma2(s0, qr[0][2*j+1], kv.y);
                fma2(s1, qr[1][2*j],   kv.x);
                fma2(s1, qr[1][2*j+1], kv.y);
            }
            float2 f0 = unpack2(s0);
            float2 f1 = unpack2(s1);
            const bool ok = (kidx < vl);
            float p0 = ok ? __expf(f0.x + f0.y + m0[kk]) : 0.f;
            float p1 = ok ? __expf(f1.x + f1.y + m1[kk]) : 0.f;
            l0 += p0;  l1 += p1;
            const u64 p0p = pack2(p0);
            const u64 p1p = pack2(p1);
            // --- PV accumulate (packed along d) ---
            const ulonglong2* vr = (const ulonglong2*)(smem + 32768 + kidx * 128);
            #pragma unroll
            for (int j = 0; j < 8; j++) {
                ulonglong2 vv = vr[j];
                fma2(acc[0][2*j],   p0p, vv.x);
                fma2(acc[0][2*j+1], p0p, vv.y);
                fma2(acc[1][2*j],   p1p, vv.x);
                fma2(acc[1][2*j+1], p1p, vv.y);
            }
        }
    }

    const u64 inv0 = pack2(1.f / l0);
    const u64 inv1 = pack2(1.f / l1);
    #pragma unroll
    for (int qi = 0; qi < 2; qi++) {
        ulonglong2* gO = (ulonglong2*)(out + ((size_t)b * Qn + tid + qi * NT) * D);
        const u64 inv = qi ? inv1 : inv0;
        #pragma unroll
        for (int j = 0; j < 8; j++) {
            ulonglong2 r;
            r.x = mul2(acc[qi][2*j],   inv);
            r.y = mul2(acc[qi][2*j+1], inv);
            gO[j] = r;
        }
    }
}

extern "C" void kernel_launch(void* const* d_in, const int* in_sizes, int n_in,
                              void* d_out, int out_size) {
    const float* q    = (const float*)d_in[0];
    const float* k    = (const float*)d_in[1];
    const float* v    = (const float*)d_in[2];
    const int*   vlen = (const int*)d_in[3];
    const float* mask = (const float*)d_in[4];
    float* out = (float*)d_out;

    const int n = in_sizes[3];
    const int smem_bytes = 2 * Kn * D * (int)sizeof(float);  // 64KB

    static bool attr_set = false;
    if (!attr_set) {
        cudaFuncSetAttribute(attn_fp32x2_kernel,
                             cudaFuncAttributeMaxDynamicSharedMemorySize,
                             smem_bytes);
        attr_set = true;
    }

    attn_fp32x2_kernel<<<n, NT, smem_bytes>>>(q, k, v, vlen, mask, out);
}